// round 5
// baseline (speedup 1.0000x reference)
#include <cuda_runtime.h>
#include <cstdint>

// Perception3D: 7-point stencil, 5 output groups per input channel.
// in : [B=4, C=16, D=64, H=64, W=64] fp32
// out: [B=4, C*G=80, D=64, H=64, W=64] fp32, out channel = c*5+g
//   g=0 ident, g=1 6-neighbor sum, g=2 gx, g=3 gy, g=4 gz (zero-padded shifts)
//
// R5: compute into SMEM, then emit each CTA's output as five 8KB TMA bulk
// stores (cp.async.bulk shared->global) with L2 evict_first policy. Goal:
// long sequential DRAM write bursts per plane instead of interleaved per-warp
// STG streams.

#define Dz 64
#define Hy 64
#define Wx 64
#define PLANE (Dz * Hy * Wx)
#define ROW   Wx
#define SLAB  (Hy * Wx)
#define W8    (Wx / 8)
#define G 5
#define HTILE 32                  // h rows per CTA
#define TILE_ELEMS (HTILE * Wx)   // 2048 floats = 8KB per plane

__device__ __forceinline__ void ld8(const float* p, float* v) {
    asm("ld.global.nc.v8.f32 {%0,%1,%2,%3,%4,%5,%6,%7}, [%8];"
        : "=f"(v[0]), "=f"(v[1]), "=f"(v[2]), "=f"(v[3]),
          "=f"(v[4]), "=f"(v[5]), "=f"(v[6]), "=f"(v[7])
        : "l"(p));
}

__device__ __forceinline__ void ld8z(const float* p, float* v, bool ok) {
    if (ok) {
        ld8(p, v);
    } else {
#pragma unroll
        for (int i = 0; i < 8; i++) v[i] = 0.f;
    }
}

__device__ __forceinline__ void st_smem8(float* s, const float* v) {
    float4 a = make_float4(v[0], v[1], v[2], v[3]);
    float4 b = make_float4(v[4], v[5], v[6], v[7]);
    *reinterpret_cast<float4*>(s)     = a;
    *reinterpret_cast<float4*>(s + 4) = b;
}

__global__ void __launch_bounds__(256)
perception3d_kernel(const float* __restrict__ in, float* __restrict__ out) {
    __shared__ float sm[G][TILE_ELEMS];   // 5 * 8KB = 40KB

    // blockIdx.x over bc(64) * d(64) * hh(2) = 8192
    unsigned bid = blockIdx.x;
    unsigned hh  = bid & 1;
    unsigned d   = (bid >> 1) & (Dz - 1);
    unsigned bc  = bid >> 7;

    unsigned t  = threadIdx.x;            // 256 threads
    unsigned w8 = t & (W8 - 1);           // 0..7
    unsigned hl = t >> 3;                 // 0..31
    unsigned h  = hh * HTILE + hl;

    const float* base = in + (size_t)bc * PLANE + (size_t)d * SLAB + (size_t)h * ROW + (size_t)w8 * 8;

    float c[8], xp[8], xm[8], yp[8], ym[8];
    ld8(base, c);
    ld8z(base + SLAB, xp, d + 1 < Dz);
    ld8z(base - SLAB, xm, d >= 1);
    ld8z(base + ROW,  yp, h + 1 < Hy);
    ld8z(base - ROW,  ym, h >= 1);

    float nextv = (w8 + 1 < W8) ? __ldg(base + 8) : 0.f;
    float prevv = (w8 >= 1)     ? __ldg(base - 1) : 0.f;

    float zp[8], zm[8];
#pragma unroll
    for (int i = 0; i < 8; i++) {
        zp[i] = (i < 7) ? c[i + 1] : nextv;
        zm[i] = (i > 0) ? c[i - 1] : prevv;
    }

    float ns[8], gx[8], gy[8], gz[8];
#pragma unroll
    for (int i = 0; i < 8; i++) {
        ns[i] = xp[i] + xm[i] + yp[i] + ym[i] + zp[i] + zm[i];
        gx[i] = xp[i] - xm[i];
        gy[i] = yp[i] - ym[i];
        gz[i] = zp[i] - zm[i];
    }

    unsigned idx = hl * ROW + w8 * 8;
    st_smem8(&sm[0][idx], c);
    st_smem8(&sm[1][idx], ns);
    st_smem8(&sm[2][idx], gx);
    st_smem8(&sm[3][idx], gy);
    st_smem8(&sm[4][idx], gz);

    // Make SMEM writes visible to the async proxy, then sync.
    asm volatile("fence.proxy.async.shared::cta;" ::: "memory");
    __syncthreads();

    if (t == 0) {
        unsigned b  = bc >> 4;
        unsigned cc = bc & 15;
        size_t tile_off = (size_t)d * SLAB + (size_t)hh * HTILE * ROW;
        float* ob = out + (size_t)b * (16 * G * PLANE) + (size_t)(cc * G) * PLANE + tile_off;

        uint64_t pol;
        asm("createpolicy.fractional.L2::evict_first.b64 %0, 1.0;" : "=l"(pol));

#pragma unroll
        for (int g = 0; g < G; g++) {
            uint32_t saddr;
            asm("{ .reg .u64 tt; cvta.to.shared.u64 tt, %1; cvt.u32.u64 %0, tt; }"
                : "=r"(saddr) : "l"(&sm[g][0]));
            float* dst = ob + (size_t)g * PLANE;
            asm volatile(
                "cp.async.bulk.global.shared::cta.bulk_group.L2::cache_hint "
                "[%0], [%1], %2, %3;"
                :: "l"(dst), "r"(saddr), "r"((unsigned)(TILE_ELEMS * 4)), "l"(pol)
                : "memory");
        }
        asm volatile("cp.async.bulk.commit_group;" ::: "memory");
        asm volatile("cp.async.bulk.wait_group 0;" ::: "memory");
    }
}

extern "C" void kernel_launch(void* const* d_in, const int* in_sizes, int n_in,
                              void* d_out, int out_size) {
    const float* in = (const float*)d_in[0];
    float* out = (float*)d_out;
    perception3d_kernel<<<8192, 256>>>(in, out);
}

// round 6
// speedup vs baseline: 1.0767x; 1.0767x over previous
#include <cuda_runtime.h>
#include <cstdint>

// Perception3D: 7-point stencil, 5 output groups per input channel.
// in : [B=4, C=16, D=64, H=64, W=64] fp32
// out: [B=4, C*G=80, D=64, H=64, W=64] fp32, out channel = c*5+g
//   g=0 ident, g=1 6-neighbor sum, g=2 gx, g=3 gy, g=4 gz (zero-padded shifts)
//
// R6: identical to R4 (v8.f32 256-bit loads/stores, fused) except the store
// policy: st.global.wt (write-through) instead of .cs. Single-variable test
// of the L2 dirty-eviction drain vs immediate write-through to DRAM.

#define Dz 64
#define Hy 64
#define Wx 64
#define PLANE (Dz * Hy * Wx)
#define ROW   Wx
#define SLAB  (Hy * Wx)
#define W8    (Wx / 8)
#define G 5

__device__ __forceinline__ void ld8(const float* p, float* v) {
    asm("ld.global.nc.v8.f32 {%0,%1,%2,%3,%4,%5,%6,%7}, [%8];"
        : "=f"(v[0]), "=f"(v[1]), "=f"(v[2]), "=f"(v[3]),
          "=f"(v[4]), "=f"(v[5]), "=f"(v[6]), "=f"(v[7])
        : "l"(p));
}

__device__ __forceinline__ void ld8z(const float* p, float* v, bool ok) {
    if (ok) {
        ld8(p, v);
    } else {
#pragma unroll
        for (int i = 0; i < 8; i++) v[i] = 0.f;
    }
}

__device__ __forceinline__ void st8wt(float* p, const float* v) {
    asm volatile("st.global.wt.v8.f32 [%0], {%1,%2,%3,%4,%5,%6,%7,%8};"
        :: "l"(p),
           "f"(v[0]), "f"(v[1]), "f"(v[2]), "f"(v[3]),
           "f"(v[4]), "f"(v[5]), "f"(v[6]), "f"(v[7])
        : "memory");
}

__global__ void __launch_bounds__(256)
perception3d_kernel(const float* __restrict__ in, float* __restrict__ out) {
    // tid over BC * D * H * W8 = 64*64*64*8 = 2,097,152
    unsigned tid = blockIdx.x * blockDim.x + threadIdx.x;

    unsigned w8 = tid & (W8 - 1);          // 0..7
    unsigned h  = (tid >> 3) & (Hy - 1);   // 0..63
    unsigned d  = (tid >> 9) & (Dz - 1);   // 0..63
    unsigned bc = tid >> 15;               // 0..63

    const float* base = in + (size_t)bc * PLANE + (size_t)d * SLAB + (size_t)h * ROW + (size_t)w8 * 8;

    float c[8], xp[8], xm[8], yp[8], ym[8];
    ld8(base, c);
    ld8z(base + SLAB, xp, d + 1 < Dz);
    ld8z(base - SLAB, xm, d >= 1);
    ld8z(base + ROW,  yp, h + 1 < Hy);
    ld8z(base - ROW,  ym, h >= 1);

    float nextv = (w8 + 1 < W8) ? __ldg(base + 8) : 0.f;
    float prevv = (w8 >= 1)     ? __ldg(base - 1) : 0.f;

    float zp[8], zm[8];
#pragma unroll
    for (int i = 0; i < 8; i++) {
        zp[i] = (i < 7) ? c[i + 1] : nextv;
        zm[i] = (i > 0) ? c[i - 1] : prevv;
    }

    float ns[8], gx[8], gy[8], gz[8];
#pragma unroll
    for (int i = 0; i < 8; i++) {
        ns[i] = xp[i] + xm[i] + yp[i] + ym[i] + zp[i] + zm[i];
        gx[i] = xp[i] - xm[i];
        gy[i] = yp[i] - ym[i];
        gz[i] = zp[i] - zm[i];
    }

    unsigned b  = bc >> 4;
    unsigned cc = bc & 15;
    size_t spatial = (size_t)d * SLAB + (size_t)h * ROW + (size_t)w8 * 8;
    float* ob = out + (size_t)b * (16 * G * PLANE) + (size_t)(cc * G) * PLANE + spatial;

    st8wt(ob,             c);
    st8wt(ob + 1 * PLANE, ns);
    st8wt(ob + 2 * PLANE, gx);
    st8wt(ob + 3 * PLANE, gy);
    st8wt(ob + 4 * PLANE, gz);
}

extern "C" void kernel_launch(void* const* d_in, const int* in_sizes, int n_in,
                              void* d_out, int out_size) {
    const float* in = (const float*)d_in[0];
    float* out = (float*)d_out;
    // 2,097,152 threads / 256 = 8192 blocks
    perception3d_kernel<<<8192, 256>>>(in, out);
}